// round 1
// baseline (speedup 1.0000x reference)
#include <cuda_runtime.h>
#include <cuda_bf16.h>
#include <mma.h>

using namespace nvcuda;

#define T_   4
#define B_   32
#define C_   384
#define N_   256
#define H_   8
#define D_   48
#define TB_  (T_ * B_)
#define TBH_ (TB_ * H_)
#define BCN_ (B_ * C_ * N_)     // one timestep slice: 3,145,728
#define TOT_ (T_ * BCN_)        // 12,582,912

// ---------------- scratch (device globals; no allocations allowed) ----------------
__device__ __nv_bfloat16 g_s1[TOT_];          // spikes after lif1, [tb][c][n]
__device__ __nv_bfloat16 g_s2[TOT_];          // spikes after attn-lif, [tb][c][n]
__device__ __nv_bfloat16 g_q[TOT_];           // [(tb*8+h)][n][d]
__device__ __nv_bfloat16 g_k[TOT_];
__device__ __nv_bfloat16 g_v[TOT_];
__device__ float         g_y[TOT_];           // fp32 staging (branch pre-LIF / attn out)
__device__ __nv_bfloat16 g_whi[4 * C_ * C_];  // bf16-hi of q_w,k_w,v_w,proj_w
__device__ __nv_bfloat16 g_wlo[4 * C_ * C_];  // bf16-lo residual

// ---------------- weight split: W = hi + lo (bf16 pair ~ fp32 precise) ------------
__global__ void wconv_kernel(const float* __restrict__ w0, const float* __restrict__ w1,
                             const float* __restrict__ w2, const float* __restrict__ w3)
{
    int i = blockIdx.x * 256 + threadIdx.x;
    if (i >= 4 * C_ * C_) return;
    int s = i / (C_ * C_);
    int j = i - s * (C_ * C_);
    const float* w = (s == 0) ? w0 : (s == 1) ? w1 : (s == 2) ? w2 : w3;
    float val = w[j];
    __nv_bfloat16 hi = __float2bfloat16(val);
    g_whi[i] = hi;
    g_wlo[i] = __float2bfloat16(val - __bfloat162float(hi));
}

// ---------------- LIF over leading time dim: h = v + (x-v)/2; spike if h>=1 -------
// Generic: fp32 input [t*BCN + i] -> bf16 spikes same layout.
__global__ void lif_kernel(const float* __restrict__ xin, __nv_bfloat16* __restrict__ sout)
{
    int i = blockIdx.x * 256 + threadIdx.x;
    if (i >= BCN_) return;
    float v = 0.f;
#pragma unroll
    for (int t = 0; t < T_; t++) {
        float xv = xin[(size_t)t * BCN_ + i];
        float h = v + (xv - v) * 0.5f;
        bool sp = (h >= 1.0f);
        sout[(size_t)t * BCN_ + i] = __float2bfloat16(sp ? 1.f : 0.f);
        v = sp ? 0.f : h;
    }
}

// LIF + head-layout transpose for q/k/v: output [(tb*8+h)][n][d]
__global__ void lif_head_kernel(const float* __restrict__ y, __nv_bfloat16* __restrict__ out)
{
    int i = blockIdx.x * 256 + threadIdx.x;
    if (i >= BCN_) return;
    int n = i & (N_ - 1);
    int c = (i >> 8) % C_;
    int b = i / (C_ * N_);
    int hh = c / D_;
    int dd = c - hh * D_;
    size_t obase = ((size_t)hh * N_ + n) * D_ + dd;
    float v = 0.f;
#pragma unroll
    for (int t = 0; t < T_; t++) {
        float xv = y[(size_t)t * BCN_ + i];
        float h = v + (xv - v) * 0.5f;
        bool sp = (h >= 1.0f);
        out[(size_t)(t * B_ + b) * (H_ * N_ * D_) + obase] = __float2bfloat16(sp ? 1.f : 0.f);
        v = sp ? 0.f : h;
    }
}

// ---------------- batched GEMM + BN (wmma bf16, split-precision A) ----------------
// Y[tb][o][n] = BN( sum_c (Whi+Wlo)[o][c] * S[tb][c][n] ) (+ bias)
#define BM 128
#define BN 64
#define BK 32

__global__ __launch_bounds__(256)
void gemm_bn_kernel(const __nv_bfloat16* __restrict__ Ahi,
                    const __nv_bfloat16* __restrict__ Alo,
                    const __nv_bfloat16* __restrict__ Bmat,
                    const float* __restrict__ gamma, const float* __restrict__ beta,
                    const float* __restrict__ mean,  const float* __restrict__ var,
                    const float* __restrict__ bias,
                    float* __restrict__ out)
{
    __shared__ __nv_bfloat16 As[BM * BK];   // 8 KB
    __shared__ __nv_bfloat16 Bs[BK * BN];   // 4 KB
    __shared__ float         Cs[BM * BN];   // 32 KB

    int o0 = blockIdx.x * BM;
    int n0 = blockIdx.y * BN;
    int tb = blockIdx.z;
    const __nv_bfloat16* Bp = Bmat + (size_t)tb * C_ * N_;
    int tid = threadIdx.x;
    int wid = tid >> 5;
    int wm = wid & 3, wn = wid >> 2;   // 4 x 2 warp grid, 32x32 per warp

    wmma::fragment<wmma::accumulator, 16, 16, 16, float> acc[2][2];
#pragma unroll
    for (int i = 0; i < 2; i++)
#pragma unroll
        for (int j = 0; j < 2; j++) wmma::fill_fragment(acc[i][j], 0.f);

    for (int kk = 0; kk < 2 * C_; kk += BK) {
        const __nv_bfloat16* Ap = (kk < C_) ? Ahi : Alo;
        int ka = (kk < C_) ? kk : (kk - C_);
        // A tile 128x32 (row-major o,c), 16B vector loads
#pragma unroll
        for (int s = 0; s < 2; s++) {
            int idx = tid + 256 * s;
            int r = idx >> 2;
            int cc = (idx & 3) << 3;
            *(uint4*)(As + r * BK + cc) = *(const uint4*)(Ap + (size_t)(o0 + r) * C_ + ka + cc);
        }
        // B tile 32x64 (row-major k,n)
        {
            int r = tid >> 3;
            int cc = (tid & 7) << 3;
            *(uint4*)(Bs + r * BN + cc) = *(const uint4*)(Bp + (size_t)(ka + r) * N_ + n0 + cc);
        }
        __syncthreads();
#pragma unroll
        for (int ks = 0; ks < BK; ks += 16) {
            wmma::fragment<wmma::matrix_a, 16, 16, 16, __nv_bfloat16, wmma::row_major> af[2];
            wmma::fragment<wmma::matrix_b, 16, 16, 16, __nv_bfloat16, wmma::row_major> bfr[2];
#pragma unroll
            for (int i = 0; i < 2; i++)
                wmma::load_matrix_sync(af[i], As + (wm * 32 + i * 16) * BK + ks, BK);
#pragma unroll
            for (int j = 0; j < 2; j++)
                wmma::load_matrix_sync(bfr[j], Bs + ks * BN + wn * 32 + j * 16, BN);
#pragma unroll
            for (int i = 0; i < 2; i++)
#pragma unroll
                for (int j = 0; j < 2; j++)
                    wmma::mma_sync(acc[i][j], af[i], bfr[j], acc[i][j]);
        }
        __syncthreads();
    }

#pragma unroll
    for (int i = 0; i < 2; i++)
#pragma unroll
        for (int j = 0; j < 2; j++)
            wmma::store_matrix_sync(Cs + (wm * 32 + i * 16) * BN + wn * 32 + j * 16,
                                    acc[i][j], BN, wmma::mem_row_major);
    __syncthreads();

#pragma unroll
    for (int s = 0; s < 32; s++) {
        int idx = tid + 256 * s;
        int r = idx >> 6;
        int cc = idx & 63;
        int o = o0 + r;
        float inv = gamma[o] / sqrtf(var[o] + 1e-5f);
        float add = beta[o] - mean[o] * inv;
        if (bias) add += bias[o] * inv;
        out[((size_t)tb * C_ + o) * N_ + n0 + cc] = Cs[r * BN + cc] * inv + add;
    }
}

// ---------------- attention: per (t,b,h): O = (Q K^T) V * 0.125 -------------------
// q,k,v binary -> all intermediates exact integers; safe to reassociate.
__global__ __launch_bounds__(256)
void attn_kernel(const __nv_bfloat16* __restrict__ q, const __nv_bfloat16* __restrict__ k,
                 const __nv_bfloat16* __restrict__ v, float* __restrict__ out)
{
    extern __shared__ float sm[];
    float* Ks = sm;             // 256*48 fp32 = 48 KB
    float* Vs = sm + N_ * D_;   // 48 KB
    int blk = blockIdx.x;       // (t*B+b)*8 + h
    size_t base = (size_t)blk * (N_ * D_);

    for (int idx = threadIdx.x; idx < N_ * D_; idx += 256) {
        Ks[idx] = __bfloat162float(k[base + idx]);
        Vs[idx] = __bfloat162float(v[base + idx]);
    }
    __syncthreads();

    int n = threadIdx.x;
    float qr[D_], acc[D_];
#pragma unroll
    for (int d = 0; d < D_; d++) {
        qr[d] = __bfloat162float(q[base + (size_t)n * D_ + d]);
        acc[d] = 0.f;
    }

    for (int m = 0; m < N_; m++) {
        const float* Kr = Ks + m * D_;
        float a0 = 0, a1 = 0, a2 = 0, a3 = 0;
#pragma unroll
        for (int d = 0; d < D_; d += 4) {
            a0 += qr[d]     * Kr[d];
            a1 += qr[d + 1] * Kr[d + 1];
            a2 += qr[d + 2] * Kr[d + 2];
            a3 += qr[d + 3] * Kr[d + 3];
        }
        float a = (a0 + a1) + (a2 + a3);
        const float* Vr = Vs + m * D_;
#pragma unroll
        for (int d = 0; d < D_; d++) acc[d] += a * Vr[d];
    }

    int t = blk / (B_ * H_);
    int rem = blk - t * (B_ * H_);
    int b = rem >> 3;
    int hh = rem & 7;
    size_t ob = (((size_t)(t * B_ + b)) * C_ + hh * D_) * N_ + n;
#pragma unroll
    for (int d = 0; d < D_; d++) out[ob + (size_t)d * N_] = acc[d] * 0.125f;
}

// ---------------- launch ----------------------------------------------------------
extern "C" void kernel_launch(void* const* d_in, const int* in_sizes, int n_in,
                              void* d_out, int out_size)
{
    const float* x   = (const float*)d_in[0];
    // d_in[1] = alpha (surrogate-grad only; unused in forward)
    const float* qw  = (const float*)d_in[2];
    const float* qg  = (const float*)d_in[3];
    const float* qb  = (const float*)d_in[4];
    const float* qm  = (const float*)d_in[5];
    const float* qv  = (const float*)d_in[6];
    const float* kw  = (const float*)d_in[7];
    const float* kg  = (const float*)d_in[8];
    const float* kb  = (const float*)d_in[9];
    const float* km  = (const float*)d_in[10];
    const float* kv  = (const float*)d_in[11];
    const float* vw  = (const float*)d_in[12];
    const float* vg  = (const float*)d_in[13];
    const float* vb  = (const float*)d_in[14];
    const float* vm  = (const float*)d_in[15];
    const float* vv  = (const float*)d_in[16];
    const float* pw  = (const float*)d_in[17];
    const float* pbias = (const float*)d_in[18];
    const float* pg  = (const float*)d_in[19];
    const float* pb  = (const float*)d_in[20];
    const float* pm  = (const float*)d_in[21];
    const float* pv  = (const float*)d_in[22];

    void *ps1, *ps2, *pq, *pk, *pvv, *py, *phi, *plo;
    cudaGetSymbolAddress(&ps1, g_s1);
    cudaGetSymbolAddress(&ps2, g_s2);
    cudaGetSymbolAddress(&pq,  g_q);
    cudaGetSymbolAddress(&pk,  g_k);
    cudaGetSymbolAddress(&pvv, g_v);
    cudaGetSymbolAddress(&py,  g_y);
    cudaGetSymbolAddress(&phi, g_whi);
    cudaGetSymbolAddress(&plo, g_wlo);
    __nv_bfloat16* s1  = (__nv_bfloat16*)ps1;
    __nv_bfloat16* s2  = (__nv_bfloat16*)ps2;
    __nv_bfloat16* qbf = (__nv_bfloat16*)pq;
    __nv_bfloat16* kbf = (__nv_bfloat16*)pk;
    __nv_bfloat16* vbf = (__nv_bfloat16*)pvv;
    float*         y   = (float*)py;
    __nv_bfloat16* whi = (__nv_bfloat16*)phi;
    __nv_bfloat16* wlo = (__nv_bfloat16*)plo;

    cudaFuncSetAttribute(attn_kernel, cudaFuncAttributeMaxDynamicSharedMemorySize,
                         2 * N_ * D_ * (int)sizeof(float));

    // 1) weight split
    wconv_kernel<<<(4 * C_ * C_ + 255) / 256, 256>>>(qw, kw, vw, pw);
    // 2) proj_lif on input
    lif_kernel<<<BCN_ / 256, 256>>>(x, s1);

    dim3 gg(C_ / BM, N_ / BN, TB_);
    // 3) q branch: GEMM+BN -> LIF+head layout
    gemm_bn_kernel<<<gg, 256>>>(whi + 0 * C_ * C_, wlo + 0 * C_ * C_, s1,
                                qg, qb, qm, qv, nullptr, y);
    lif_head_kernel<<<BCN_ / 256, 256>>>(y, qbf);
    // 4) k branch
    gemm_bn_kernel<<<gg, 256>>>(whi + 1 * C_ * C_, wlo + 1 * C_ * C_, s1,
                                kg, kb, km, kv, nullptr, y);
    lif_head_kernel<<<BCN_ / 256, 256>>>(y, kbf);
    // 5) v branch
    gemm_bn_kernel<<<gg, 256>>>(whi + 2 * C_ * C_, wlo + 2 * C_ * C_, s1,
                                vg, vb, vm, vv, nullptr, y);
    lif_head_kernel<<<BCN_ / 256, 256>>>(y, vbf);
    // 6) attention (Q K^T) V * 0.125 -> [T,B,C,N] fp32
    attn_kernel<<<TBH_, 256, 2 * N_ * D_ * (int)sizeof(float)>>>(qbf, kbf, vbf, y);
    // 7) attn_lif
    lif_kernel<<<BCN_ / 256, 256>>>(y, s2);
    // 8) proj GEMM + bias + BN -> final output [T,B,C,H,W]
    gemm_bn_kernel<<<gg, 256>>>(whi + 3 * C_ * C_, wlo + 3 * C_ * C_, s2,
                                pg, pb, pm, pv, pbias, (float*)d_out);
}

// round 3
// speedup vs baseline: 3.2411x; 3.2411x over previous
#include <cuda_runtime.h>
#include <cuda_bf16.h>
#include <mma.h>
#include <cstdint>

using namespace nvcuda;

#define T_   4
#define B_   32
#define C_   384
#define N_   256
#define H_   8
#define D_   48
#define TB_  (T_ * B_)
#define TBH_ (TB_ * H_)
#define BCN_ (B_ * C_ * N_)      // 3,145,728
#define TOT_ (T_ * BCN_)         // 12,582,912
#define M3_  (3 * C_)            // 1152 stacked qkv output channels
#define BON_ (B_ * M3_ * N_)     // 9,437,184 (one timestep of fused qkv out)

// ---------------- scratch (device globals; no allocation allowed) -----------------
__device__ __nv_bfloat16 g_s1[TOT_];           // spikes after lif1   [tb][c][n]
__device__ __nv_bfloat16 g_sq[TOT_];           // q spikes            [tb][c][n]
__device__ __nv_bfloat16 g_sk[TOT_];           // k spikes
__device__ __nv_bfloat16 g_sv[TOT_];           // v spikes
__device__ __nv_bfloat16 g_s2[TOT_];           // attn-lif spikes
__device__ float         g_y3[3 * TOT_];       // fused qkv GEMM out  [tb][1152][n]
__device__ float         g_ya[TOT_];           // attention out fp32  [tb][c][n]
__device__ __nv_bfloat16 g_whi[4 * C_ * C_];   // hi bf16 of q,k,v,proj weights
__device__ __nv_bfloat16 g_wlo[4 * C_ * C_];   // lo residual
__device__ float         g_bns[4 * C_];        // folded BN scale per channel
__device__ float         g_bnb[4 * C_];        // folded BN shift per channel

// ---------------- prep: weight split + BN fold -------------------------------------
__global__ void wconv_kernel(const float* __restrict__ w0, const float* __restrict__ w1,
                             const float* __restrict__ w2, const float* __restrict__ w3)
{
    int i = blockIdx.x * 256 + threadIdx.x;
    if (i >= 4 * C_ * C_) return;
    int s = i / (C_ * C_);
    int j = i - s * (C_ * C_);
    const float* w = (s == 0) ? w0 : (s == 1) ? w1 : (s == 2) ? w2 : w3;
    float val = w[j];
    __nv_bfloat16 hi = __float2bfloat16(val);
    g_whi[i] = hi;
    g_wlo[i] = __float2bfloat16(val - __bfloat162float(hi));
}

__global__ void bnfold_kernel(const float* qg, const float* qb, const float* qm, const float* qv,
                              const float* kg, const float* kb, const float* km, const float* kv,
                              const float* vg, const float* vb, const float* vm, const float* vv,
                              const float* pg, const float* pb, const float* pm, const float* pv,
                              const float* pbias)
{
    int i = blockIdx.x * 256 + threadIdx.x;
    if (i >= 4 * C_) return;
    int s = i / C_, c = i - s * C_;
    const float *G, *Bt, *M, *V;
    if      (s == 0) { G = qg; Bt = qb; M = qm; V = qv; }
    else if (s == 1) { G = kg; Bt = kb; M = km; V = kv; }
    else if (s == 2) { G = vg; Bt = vb; M = vm; V = vv; }
    else             { G = pg; Bt = pb; M = pm; V = pv; }
    float inv = G[c] / sqrtf(V[c] + 1e-5f);
    float add = Bt[c] - M[c] * inv;
    if (s == 3) add += pbias[c] * inv;
    g_bns[i] = inv;
    g_bnb[i] = add;
}

// ---------------- LIF: h = v + (x-v)/2; spike if h >= 1; hard reset ----------------
__global__ void lif_kernel(const float* __restrict__ xin, __nv_bfloat16* __restrict__ sout)
{
    int i = blockIdx.x * 256 + threadIdx.x;
    if (i >= BCN_) return;
    float v = 0.f;
#pragma unroll
    for (int t = 0; t < T_; t++) {
        float xv = xin[(size_t)t * BCN_ + i];
        float h = v + (xv - v) * 0.5f;
        bool sp = (h >= 1.0f);
        sout[(size_t)t * BCN_ + i] = __float2bfloat16(sp ? 1.f : 0.f);
        v = sp ? 0.f : h;
    }
}

// LIF over fused qkv output [t*B+b][o(1152)][n] -> three [tb][c][n] spike buffers
__global__ void lif3_kernel(const float* __restrict__ y,
                            __nv_bfloat16* __restrict__ oq,
                            __nv_bfloat16* __restrict__ ok,
                            __nv_bfloat16* __restrict__ ov)
{
    int i = blockIdx.x * 256 + threadIdx.x;
    if (i >= BON_) return;
    int n = i & (N_ - 1);
    int o = (i >> 8) % M3_;
    int b = i / (M3_ * N_);
    int s = o / C_;
    int oc = o - s * C_;
    __nv_bfloat16* outp = (s == 0) ? oq : (s == 1) ? ok : ov;
    size_t ibase = ((size_t)b * M3_ + o) * N_ + n;
    size_t obase = ((size_t)b * C_ + oc) * N_ + n;
    float v = 0.f;
#pragma unroll
    for (int t = 0; t < T_; t++) {
        float xv = y[(size_t)t * BON_ + ibase];
        float h = v + (xv - v) * 0.5f;
        bool sp = (h >= 1.0f);
        outp[(size_t)t * BCN_ + obase] = __float2bfloat16(sp ? 1.f : 0.f);
        v = sp ? 0.f : h;
    }
}

// ---------------- cp.async helpers -------------------------------------------------
__device__ __forceinline__ void cpa16(void* s, const void* g)
{
    unsigned int sa = (unsigned int)__cvta_generic_to_shared(s);
    asm volatile("cp.async.cg.shared.global [%0], [%1], 16;\n" :: "r"(sa), "l"(g));
}
__device__ __forceinline__ void cpa_commit() { asm volatile("cp.async.commit_group;\n"); }
template <int N>
__device__ __forceinline__ void cpa_wait() { asm volatile("cp.async.wait_group %0;\n" :: "n"(N)); }

// ---------------- batched GEMM + folded BN (wmma bf16, 2-stage cp.async) -----------
// out[tb][o][n] = bns[o] * sum_c (Whi+Wlo)[o][c] * S[tb][c][n] + bnb[o]
#define GBM 128
#define GBN 128
#define GBK 64
#define LDA 72      // 64 + 8 pad
#define LDB 136     // 128 + 8 pad
#define NT_ 12      // 2*C_/GBK
#define GSM (2 * GBM * LDA * 2 + 2 * GBK * LDB * 2)   // 71680 B

__global__ __launch_bounds__(256)
void gemm_bn_kernel(const __nv_bfloat16* __restrict__ Ahi,
                    const __nv_bfloat16* __restrict__ Alo,
                    const __nv_bfloat16* __restrict__ Bmat,
                    int ldo, int bnoff, float* __restrict__ out)
{
    extern __shared__ char smem[];
    __nv_bfloat16* As = (__nv_bfloat16*)smem;                        // [2][GBM][LDA]
    __nv_bfloat16* Bs = (__nv_bfloat16*)(smem + 2 * GBM * LDA * 2);  // [2][GBK][LDB]
    float*         Cs = (float*)smem;                                // reuse: GBM*GBN

    int o0 = blockIdx.x * GBM;
    int n0 = blockIdx.y * GBN;
    int tb = blockIdx.z;
    const __nv_bfloat16* Bp = Bmat + (size_t)tb * C_ * N_;
    int tid = threadIdx.x;
    int wid = tid >> 5;
    int wm = wid & 1;          // warp tile: rows wm*64.., cols wn*32..
    int wn = wid >> 1;

    wmma::fragment<wmma::accumulator, 16, 16, 16, float> acc[4][2];
#pragma unroll
    for (int i = 0; i < 4; i++)
#pragma unroll
        for (int j = 0; j < 2; j++) wmma::fill_fragment(acc[i][j], 0.f);

    auto issue = [&](int kt, int st) {
        const __nv_bfloat16* Ap = (kt < 6) ? Ahi : Alo;
        int ka = (kt < 6) ? kt * GBK : (kt - 6) * GBK;
        __nv_bfloat16* Ad = As + st * GBM * LDA;
        __nv_bfloat16* Bd = Bs + st * GBK * LDB;
#pragma unroll
        for (int u = 0; u < 4; u++) {       // A: 1024 16B chunks
            int idx = tid + u * 256;
            int r = idx >> 3, col = (idx & 7) << 3;
            cpa16(Ad + r * LDA + col, Ap + (size_t)(o0 + r) * C_ + ka + col);
        }
#pragma unroll
        for (int u = 0; u < 4; u++) {       // B: 1024 16B chunks
            int idx = tid + u * 256;
            int r = idx >> 4, col = (idx & 15) << 3;
            cpa16(Bd + r * LDB + col, Bp + (size_t)(ka + r) * N_ + n0 + col);
        }
        cpa_commit();
    };

    issue(0, 0);
    for (int kt = 0; kt < NT_; kt++) {
        if (kt + 1 < NT_) issue(kt + 1, (kt + 1) & 1);
        if (kt + 1 < NT_) cpa_wait<1>(); else cpa_wait<0>();
        __syncthreads();
        const __nv_bfloat16* Ab = As + (kt & 1) * GBM * LDA;
        const __nv_bfloat16* Bb = Bs + (kt & 1) * GBK * LDB;
#pragma unroll
        for (int ks = 0; ks < 4; ks++) {
            wmma::fragment<wmma::matrix_a, 16, 16, 16, __nv_bfloat16, wmma::row_major> af[4];
            wmma::fragment<wmma::matrix_b, 16, 16, 16, __nv_bfloat16, wmma::row_major> bfr[2];
#pragma unroll
            for (int i = 0; i < 4; i++)
                wmma::load_matrix_sync(af[i], Ab + (wm * 64 + i * 16) * LDA + ks * 16, LDA);
#pragma unroll
            for (int j = 0; j < 2; j++)
                wmma::load_matrix_sync(bfr[j], Bb + (ks * 16) * LDB + wn * 32 + j * 16, LDB);
#pragma unroll
            for (int i = 0; i < 4; i++)
#pragma unroll
                for (int j = 0; j < 2; j++)
                    wmma::mma_sync(acc[i][j], af[i], bfr[j], acc[i][j]);
        }
        __syncthreads();
    }

    // epilogue: stage to smem, apply BN, vectorized write
#pragma unroll
    for (int i = 0; i < 4; i++)
#pragma unroll
        for (int j = 0; j < 2; j++)
            wmma::store_matrix_sync(Cs + (wm * 64 + i * 16) * GBN + wn * 32 + j * 16,
                                    acc[i][j], GBN, wmma::mem_row_major);
    __syncthreads();

#pragma unroll
    for (int u = 0; u < 16; u++) {          // 4096 float4
        int e = tid + u * 256;
        int r = e >> 5;
        int c4 = (e & 31) << 2;
        int o = o0 + r;
        float inv = g_bns[bnoff + o];
        float add = g_bnb[bnoff + o];
        float4 val = *(float4*)(Cs + r * GBN + c4);
        val.x = val.x * inv + add;
        val.y = val.y * inv + add;
        val.z = val.z * inv + add;
        val.w = val.w * inv + add;
        *(float4*)(out + ((size_t)tb * ldo + o) * N_ + n0 + c4) = val;
    }
}

// ---------------- tensor-core attention -------------------------------------------
// Per (t,b,h): S = Qt K (exact int <=48 in bf16), O = V St * 0.125. Layout [d][n].
#define LDQ 264     // 256 + 8
#define LDS 72      // 64 + 8
#define ASM_ (3 * 64 * LDQ * 2 + 256 * LDS * 2 + 8 * 256 * 4 + 64 * LDS * 4)  // 164864

__global__ __launch_bounds__(256)
void attn_kernel(const __nv_bfloat16* __restrict__ q, const __nv_bfloat16* __restrict__ k,
                 const __nv_bfloat16* __restrict__ v, float* __restrict__ out)
{
    extern __shared__ char smraw[];
    __nv_bfloat16* Qs = (__nv_bfloat16*)smraw;             // [64][LDQ]
    __nv_bfloat16* Ks = Qs + 64 * LDQ;
    __nv_bfloat16* Vs = Ks + 64 * LDQ;
    __nv_bfloat16* STb = Vs + 64 * LDQ;                    // S^T [256][LDS]
    float* scratch = (float*)(STb + 256 * LDS);            // 8 warps x 256 fp32
    float* Osm = scratch + 8 * 256;                        // [64][LDS]

    int blk = blockIdx.x;
    int tb = blk >> 3, h = blk & 7;
    size_t base = ((size_t)tb * C_ + h * D_) * N_;
    int tid = threadIdx.x;
    int wid = tid >> 5;
    int lane = tid & 31;

    // load Q,K,V head slices [48][256] bf16, coalesced 16B chunks (1536 per matrix)
    const __nv_bfloat16* srcs[3] = { q + base, k + base, v + base };
    __nv_bfloat16* dsts[3] = { Qs, Ks, Vs };
#pragma unroll
    for (int mtx = 0; mtx < 3; mtx++) {
#pragma unroll
        for (int u = 0; u < 6; u++) {
            int idx = tid + u * 256;
            int r = idx >> 5, col = (idx & 31) << 3;
            *(uint4*)(dsts[mtx] + r * LDQ + col) = *(const uint4*)(srcs[mtx] + (size_t)r * N_ + col);
        }
        // zero pad rows 48..63 (d padded to 64)
#pragma unroll
        for (int u = 0; u < 2; u++) {
            int idx = tid + u * 256;
            int r = 48 + (idx >> 5), col = (idx & 31) << 3;
            *(uint4*)(dsts[mtx] + r * LDQ + col) = make_uint4(0, 0, 0, 0);
        }
    }
    __syncthreads();

    int wr = wid & 1;       // stage1: S rows (n) wr*32.., cols (m) wc*64..
    int wc = wid >> 1;

#pragma unroll 1
    for (int nt = 0; nt < 4; nt++) {
        int n0 = nt * 64;

        // ---- stage 1: S[n0+0..63][0..255] = Q^T K ----
        wmma::fragment<wmma::accumulator, 16, 16, 16, float> sacc[2][4];
#pragma unroll
        for (int i = 0; i < 2; i++)
#pragma unroll
            for (int j = 0; j < 4; j++) wmma::fill_fragment(sacc[i][j], 0.f);
#pragma unroll
        for (int dk = 0; dk < 64; dk += 16) {
            wmma::fragment<wmma::matrix_a, 16, 16, 16, __nv_bfloat16, wmma::col_major> af[2];
            wmma::fragment<wmma::matrix_b, 16, 16, 16, __nv_bfloat16, wmma::row_major> bfr[4];
#pragma unroll
            for (int i = 0; i < 2; i++)
                wmma::load_matrix_sync(af[i], Qs + dk * LDQ + n0 + wr * 32 + i * 16, LDQ);
#pragma unroll
            for (int j = 0; j < 4; j++)
                wmma::load_matrix_sync(bfr[j], Ks + dk * LDQ + wc * 64 + j * 16, LDQ);
#pragma unroll
            for (int i = 0; i < 2; i++)
#pragma unroll
                for (int j = 0; j < 4; j++)
                    wmma::mma_sync(sacc[i][j], af[i], bfr[j], sacc[i][j]);
        }
        // convert S -> bf16 S^T in smem (exact: integers <= 48)
        float* scr = scratch + wid * 256;
#pragma unroll
        for (int i = 0; i < 2; i++)
#pragma unroll
            for (int j = 0; j < 4; j++) {
                wmma::store_matrix_sync(scr, sacc[i][j], 16, wmma::mem_col_major);
                __syncwarp();
#pragma unroll
                for (int e = 0; e < 8; e++) {
                    int idx = lane + e * 32;
                    int ni = idx & 15, mj = idx >> 4;
                    STb[(wc * 64 + j * 16 + mj) * LDS + wr * 32 + i * 16 + ni] =
                        __float2bfloat16(scr[idx]);
                }
                __syncwarp();
            }
        __syncthreads();

        // ---- stage 2: O[0..63][n0..n0+63] = V S^T ----
        int dr = wid & 1;   // d rows dr*32..
        int nc = wid >> 1;  // n cols nc*16..
        wmma::fragment<wmma::accumulator, 16, 16, 16, float> oacc[2];
#pragma unroll
        for (int i = 0; i < 2; i++) wmma::fill_fragment(oacc[i], 0.f);
#pragma unroll
        for (int m = 0; m < 256; m += 16) {
            wmma::fragment<wmma::matrix_a, 16, 16, 16, __nv_bfloat16, wmma::row_major> av[2];
            wmma::fragment<wmma::matrix_b, 16, 16, 16, __nv_bfloat16, wmma::row_major> bs;
#pragma unroll
            for (int i = 0; i < 2; i++)
                wmma::load_matrix_sync(av[i], Vs + (dr * 32 + i * 16) * LDQ + m, LDQ);
            wmma::load_matrix_sync(bs, STb + m * LDS + nc * 16, LDS);
#pragma unroll
            for (int i = 0; i < 2; i++)
                wmma::mma_sync(oacc[i], av[i], bs, oacc[i]);
        }
#pragma unroll
        for (int i = 0; i < 2; i++) {
#pragma unroll
            for (int e = 0; e < oacc[i].num_elements; e++) oacc[i].x[e] *= 0.125f;
            wmma::store_matrix_sync(Osm + (dr * 32 + i * 16) * LDS + nc * 16,
                                    oacc[i], LDS, wmma::mem_row_major);
        }
        __syncthreads();

        // write d<48 rows to [tb][c][n] fp32 (768 float4)
#pragma unroll
        for (int u = 0; u < 3; u++) {
            int e = tid + u * 256;
            int d = e >> 4, c4 = (e & 15) << 2;
            float4 val = *(float4*)(Osm + d * LDS + c4);
            *(float4*)(out + base + (size_t)d * N_ + n0 + c4) = val;
        }
        __syncthreads();
    }
}

// ---------------- launch -----------------------------------------------------------
extern "C" void kernel_launch(void* const* d_in, const int* in_sizes, int n_in,
                              void* d_out, int out_size)
{
    const float* x   = (const float*)d_in[0];
    const float* qw  = (const float*)d_in[2];
    const float* qg  = (const float*)d_in[3];
    const float* qb  = (const float*)d_in[4];
    const float* qm  = (const float*)d_in[5];
    const float* qv  = (const float*)d_in[6];
    const float* kw  = (const float*)d_in[7];
    const float* kg  = (const float*)d_in[8];
    const float* kb  = (const float*)d_in[9];
    const float* km  = (const float*)d_in[10];
    const float* kv  = (const float*)d_in[11];
    const float* vw  = (const float*)d_in[12];
    const float* vg  = (const float*)d_in[13];
    const float* vb  = (const float*)d_in[14];
    const float* vm  = (const float*)d_in[15];
    const float* vv  = (const float*)d_in[16];
    const float* pw  = (const float*)d_in[17];
    const float* pbias = (const float*)d_in[18];
    const float* pg  = (const float*)d_in[19];
    const float* pb  = (const float*)d_in[20];
    const float* pm  = (const float*)d_in[21];
    const float* pv  = (const float*)d_in[22];

    void *ps1, *psq, *psk, *psv, *ps2, *py3, *pya, *phi, *plo;
    cudaGetSymbolAddress(&ps1, g_s1);
    cudaGetSymbolAddress(&psq, g_sq);
    cudaGetSymbolAddress(&psk, g_sk);
    cudaGetSymbolAddress(&psv, g_sv);
    cudaGetSymbolAddress(&ps2, g_s2);
    cudaGetSymbolAddress(&py3, g_y3);
    cudaGetSymbolAddress(&pya, g_ya);
    cudaGetSymbolAddress(&phi, g_whi);
    cudaGetSymbolAddress(&plo, g_wlo);
    __nv_bfloat16* s1  = (__nv_bfloat16*)ps1;
    __nv_bfloat16* sq  = (__nv_bfloat16*)psq;
    __nv_bfloat16* sk  = (__nv_bfloat16*)psk;
    __nv_bfloat16* sv  = (__nv_bfloat16*)psv;
    __nv_bfloat16* s2  = (__nv_bfloat16*)ps2;
    float*         y3  = (float*)py3;
    float*         ya  = (float*)pya;
    __nv_bfloat16* whi = (__nv_bfloat16*)phi;
    __nv_bfloat16* wlo = (__nv_bfloat16*)plo;

    cudaFuncSetAttribute(gemm_bn_kernel, cudaFuncAttributeMaxDynamicSharedMemorySize, GSM);
    cudaFuncSetAttribute(attn_kernel, cudaFuncAttributeMaxDynamicSharedMemorySize, ASM_);

    // prep
    wconv_kernel<<<(4 * C_ * C_ + 255) / 256, 256>>>(qw, kw, vw, pw);
    bnfold_kernel<<<6, 256>>>(qg, qb, qm, qv, kg, kb, km, kv,
                              vg, vb, vm, vv, pg, pb, pm, pv, pbias);
    // proj_lif on input
    lif_kernel<<<BCN_ / 256, 256>>>(x, s1);
    // fused q,k,v GEMM + BN  (M = 1152 stacked)
    gemm_bn_kernel<<<dim3(M3_ / GBM, N_ / GBN, TB_), 256, GSM>>>(
        whi, wlo, s1, M3_, 0, y3);
    // LIF over all three branches, natural layout
    lif3_kernel<<<BON_ / 256, 256>>>(y3, sq, sk, sv);
    // tensor-core attention
    attn_kernel<<<TBH_, 256, ASM_>>>(sq, sk, sv, ya);
    // attn_lif
    lif_kernel<<<BCN_ / 256, 256>>>(ya, s2);
    // proj GEMM + bias + BN -> final output
    gemm_bn_kernel<<<dim3(C_ / GBM, N_ / GBN, TB_), 256, GSM>>>(
        whi + 3 * C_ * C_, wlo + 3 * C_ * C_, s2, C_, 3 * C_, (float*)d_out);
}

// round 5
// speedup vs baseline: 3.6094x; 1.1136x over previous
#include <cuda_runtime.h>
#include <cuda_bf16.h>
#include <mma.h>
#include <cstdint>

using namespace nvcuda;

#define T_   4
#define B_   32
#define C_   384
#define N_   256
#define H_   8
#define D_   48
#define TB_  (T_ * B_)
#define TBH_ (TB_ * H_)
#define BCN_ (B_ * C_ * N_)      // 3,145,728
#define TOT_ (T_ * BCN_)         // 12,582,912
#define M3_  (3 * C_)            // 1152 stacked qkv output channels
#define BON_ (B_ * M3_ * N_)     // 9,437,184

// ---------------- scratch (device globals; no allocation allowed) -----------------
__device__ __nv_bfloat16 g_s1[TOT_];           // spikes after lif1   [tb][c][n]
__device__ __nv_bfloat16 g_sq[TOT_];           // q spikes            [tb][c][n]
__device__ __nv_bfloat16 g_sk[TOT_];
__device__ __nv_bfloat16 g_sv[TOT_];
__device__ __nv_bfloat16 g_s2[TOT_];           // attn-lif spikes
__device__ float         g_y3[3 * TOT_];       // fused qkv GEMM out  [tb][1152][n]
__device__ float         g_ya[TOT_];           // attention out fp32  [tb][c][n]
__device__ __nv_bfloat16 g_whi[4 * C_ * C_];   // hi bf16 of q,k,v,proj weights
__device__ __nv_bfloat16 g_wlo[4 * C_ * C_];   // lo residual
__device__ float         g_bns[4 * C_];
__device__ float         g_bnb[4 * C_];

// ---------------- prep ------------------------------------------------------------
__global__ void wconv_kernel(const float* __restrict__ w0, const float* __restrict__ w1,
                             const float* __restrict__ w2, const float* __restrict__ w3)
{
    int i = blockIdx.x * 256 + threadIdx.x;
    if (i >= 4 * C_ * C_) return;
    int s = i / (C_ * C_);
    int j = i - s * (C_ * C_);
    const float* w = (s == 0) ? w0 : (s == 1) ? w1 : (s == 2) ? w2 : w3;
    float val = w[j];
    __nv_bfloat16 hi = __float2bfloat16(val);
    g_whi[i] = hi;
    g_wlo[i] = __float2bfloat16(val - __bfloat162float(hi));
}

__global__ void bnfold_kernel(const float* qg, const float* qb, const float* qm, const float* qv,
                              const float* kg, const float* kb, const float* km, const float* kv,
                              const float* vg, const float* vb, const float* vm, const float* vv,
                              const float* pg, const float* pb, const float* pm, const float* pv,
                              const float* pbias)
{
    int i = blockIdx.x * 256 + threadIdx.x;
    if (i >= 4 * C_) return;
    int s = i / C_, c = i - s * C_;
    const float *G, *Bt, *M, *V;
    if      (s == 0) { G = qg; Bt = qb; M = qm; V = qv; }
    else if (s == 1) { G = kg; Bt = kb; M = km; V = kv; }
    else if (s == 2) { G = vg; Bt = vb; M = vm; V = vv; }
    else             { G = pg; Bt = pb; M = pm; V = pv; }
    float inv = G[c] / sqrtf(V[c] + 1e-5f);
    float add = Bt[c] - M[c] * inv;
    if (s == 3) add += pbias[c] * inv;
    g_bns[i] = inv;
    g_bnb[i] = add;
}

// ---------------- LIF -------------------------------------------------------------
__global__ void lif_kernel(const float* __restrict__ xin, __nv_bfloat16* __restrict__ sout)
{
    int i = blockIdx.x * 256 + threadIdx.x;
    if (i >= BCN_) return;
    float v = 0.f;
#pragma unroll
    for (int t = 0; t < T_; t++) {
        float xv = xin[(size_t)t * BCN_ + i];
        float h = v + (xv - v) * 0.5f;
        bool sp = (h >= 1.0f);
        sout[(size_t)t * BCN_ + i] = __float2bfloat16(sp ? 1.f : 0.f);
        v = sp ? 0.f : h;
    }
}

__global__ void lif3_kernel(const float* __restrict__ y,
                            __nv_bfloat16* __restrict__ oq,
                            __nv_bfloat16* __restrict__ ok,
                            __nv_bfloat16* __restrict__ ov)
{
    int i = blockIdx.x * 256 + threadIdx.x;
    if (i >= BON_) return;
    int n = i & (N_ - 1);
    int o = (i >> 8) % M3_;
    int b = i / (M3_ * N_);
    int s = o / C_;
    int oc = o - s * C_;
    __nv_bfloat16* outp = (s == 0) ? oq : (s == 1) ? ok : ov;
    size_t ibase = ((size_t)b * M3_ + o) * N_ + n;
    size_t obase = ((size_t)b * C_ + oc) * N_ + n;
    float v = 0.f;
#pragma unroll
    for (int t = 0; t < T_; t++) {
        float xv = y[(size_t)t * BON_ + ibase];
        float h = v + (xv - v) * 0.5f;
        bool sp = (h >= 1.0f);
        outp[(size_t)t * BCN_ + obase] = __float2bfloat16(sp ? 1.f : 0.f);
        v = sp ? 0.f : h;
    }
}

// ---------------- cp.async helpers ------------------------------------------------
__device__ __forceinline__ void cpa16(void* s, const void* g)
{
    unsigned int sa = (unsigned int)__cvta_generic_to_shared(s);
    asm volatile("cp.async.cg.shared.global [%0], [%1], 16;\n" :: "r"(sa), "l"(g));
}
__device__ __forceinline__ void cpa_commit() { asm volatile("cp.async.commit_group;\n"); }
template <int N>
__device__ __forceinline__ void cpa_wait() { asm volatile("cp.async.wait_group %0;\n" :: "n"(N)); }

// ---------------- batched GEMM + folded BN (hi/lo share B tile) -------------------
// out[tb][o][n] = bns[o] * sum_c (Whi+Wlo)[o][c] * S[tb][c][n] + bnb[o]
#define GBM 128
#define GBN 128
#define GBK 64
#define LDA 72      // 64 + 8 pad
#define LDB 136     // 128 + 8 pad
#define NT_ 6       // C_/GBK
#define ASTG (2 * GBM * LDA)                       // hi + lo per stage (elems)
#define GSM ((2 * ASTG + 2 * GBK * LDB) * 2)       // 108544 B

__global__ __launch_bounds__(256, 2)
void gemm_bn_kernel(const __nv_bfloat16* __restrict__ Ahi,
                    const __nv_bfloat16* __restrict__ Alo,
                    const __nv_bfloat16* __restrict__ Bmat,
                    int ldo, int bnoff, float* __restrict__ out)
{
    extern __shared__ char smem[];
    __nv_bfloat16* As = (__nv_bfloat16*)smem;                    // [2][2][GBM][LDA]
    __nv_bfloat16* Bs = (__nv_bfloat16*)(smem + 2 * ASTG * 2);   // [2][GBK][LDB]
    float*         Cs = (float*)smem;                            // epilogue reuse

    int o0 = blockIdx.x * GBM;
    int n0 = blockIdx.y * GBN;
    int tb = blockIdx.z;
    const __nv_bfloat16* Bp = Bmat + (size_t)tb * C_ * N_;
    int tid = threadIdx.x;
    int wid = tid >> 5;
    int wm = wid & 1;          // rows wm*64.., cols wn*32..
    int wn = wid >> 1;

    wmma::fragment<wmma::accumulator, 16, 16, 16, float> acc[4][2];
#pragma unroll
    for (int i = 0; i < 4; i++)
#pragma unroll
        for (int j = 0; j < 2; j++) wmma::fill_fragment(acc[i][j], 0.f);

    auto issue = [&](int kt, int st) {
        int ka = kt * GBK;
        __nv_bfloat16* Ad = As + st * ASTG;          // hi
        __nv_bfloat16* Al = Ad + GBM * LDA;          // lo
        __nv_bfloat16* Bd = Bs + st * GBK * LDB;
#pragma unroll
        for (int u = 0; u < 4; u++) {                // A hi+lo: 1024 chunks each
            int idx = tid + u * 256;
            int r = idx >> 3, col = (idx & 7) << 3;
            size_t go = (size_t)(o0 + r) * C_ + ka + col;
            cpa16(Ad + r * LDA + col, Ahi + go);
            cpa16(Al + r * LDA + col, Alo + go);
        }
#pragma unroll
        for (int u = 0; u < 4; u++) {                // B: 1024 chunks
            int idx = tid + u * 256;
            int r = idx >> 4, col = (idx & 15) << 3;
            cpa16(Bd + r * LDB + col, Bp + (size_t)(ka + r) * N_ + n0 + col);
        }
        cpa_commit();
    };

    issue(0, 0);
    for (int kt = 0; kt < NT_; kt++) {
        if (kt + 1 < NT_) issue(kt + 1, (kt + 1) & 1);
        if (kt + 1 < NT_) cpa_wait<1>(); else cpa_wait<0>();
        __syncthreads();
        const __nv_bfloat16* Ah = As + (kt & 1) * ASTG;
        const __nv_bfloat16* Al = Ah + GBM * LDA;
        const __nv_bfloat16* Bb = Bs + (kt & 1) * GBK * LDB;
#pragma unroll
        for (int ks = 0; ks < 4; ks++) {
            wmma::fragment<wmma::matrix_b, 16, 16, 16, __nv_bfloat16, wmma::row_major> bfr[2];
#pragma unroll
            for (int j = 0; j < 2; j++)
                wmma::load_matrix_sync(bfr[j], Bb + (ks * 16) * LDB + wn * 32 + j * 16, LDB);
            wmma::fragment<wmma::matrix_a, 16, 16, 16, __nv_bfloat16, wmma::row_major> af[4];
#pragma unroll
            for (int i = 0; i < 4; i++)
                wmma::load_matrix_sync(af[i], Ah + (wm * 64 + i * 16) * LDA + ks * 16, LDA);
#pragma unroll
            for (int i = 0; i < 4; i++)
#pragma unroll
                for (int j = 0; j < 2; j++)
                    wmma::mma_sync(acc[i][j], af[i], bfr[j], acc[i][j]);
#pragma unroll
            for (int i = 0; i < 4; i++)
                wmma::load_matrix_sync(af[i], Al + (wm * 64 + i * 16) * LDA + ks * 16, LDA);
#pragma unroll
            for (int i = 0; i < 4; i++)
#pragma unroll
                for (int j = 0; j < 2; j++)
                    wmma::mma_sync(acc[i][j], af[i], bfr[j], acc[i][j]);
        }
        __syncthreads();
    }

    // epilogue: stage to smem, apply BN, vectorized write
#pragma unroll
    for (int i = 0; i < 4; i++)
#pragma unroll
        for (int j = 0; j < 2; j++)
            wmma::store_matrix_sync(Cs + (wm * 64 + i * 16) * GBN + wn * 32 + j * 16,
                                    acc[i][j], GBN, wmma::mem_row_major);
    __syncthreads();

#pragma unroll
    for (int u = 0; u < 16; u++) {
        int e = tid + u * 256;
        int r = e >> 5;
        int c4 = (e & 31) << 2;
        int o = o0 + r;
        float inv = g_bns[bnoff + o];
        float add = g_bnb[bnoff + o];
        float4 val = *(float4*)(Cs + r * GBN + c4);
        val.x = val.x * inv + add;
        val.y = val.y * inv + add;
        val.z = val.z * inv + add;
        val.w = val.w * inv + add;
        *(float4*)(out + ((size_t)tb * ldo + o) * N_ + n0 + c4) = val;
    }
}

// ---------------- tensor-core attention -------------------------------------------
#define LDQ 264     // 256 + 8
#define LDS 72      // 64 + 8
#define ASM_ (3 * 64 * LDQ * 2 + 256 * LDS * 2 + 8 * 256 * 4 + 64 * LDS * 4)  // 164864

__global__ __launch_bounds__(256)
void attn_kernel(const __nv_bfloat16* __restrict__ q, const __nv_bfloat16* __restrict__ k,
                 const __nv_bfloat16* __restrict__ v, float* __restrict__ out)
{
    extern __shared__ char smraw[];
    __nv_bfloat16* Qs = (__nv_bfloat16*)smraw;             // [64][LDQ]
    __nv_bfloat16* Ks = Qs + 64 * LDQ;
    __nv_bfloat16* Vs = Ks + 64 * LDQ;
    __nv_bfloat16* STb = Vs + 64 * LDQ;                    // S^T [256][LDS]
    float* scratch = (float*)(STb + 256 * LDS);
    float* Osm = scratch + 8 * 256;                        // [64][LDS]

    int blk = blockIdx.x;
    int tb = blk >> 3, h = blk & 7;
    size_t base = ((size_t)tb * C_ + h * D_) * N_;
    int tid = threadIdx.x;
    int wid = tid >> 5;
    int lane = tid & 31;

    const __nv_bfloat16* srcs[3] = { q + base, k + base, v + base };
    __nv_bfloat16* dsts[3] = { Qs, Ks, Vs };
#pragma unroll
    for (int mtx = 0; mtx < 3; mtx++) {
#pragma unroll
        for (int u = 0; u < 6; u++) {
            int idx = tid + u * 256;
            int r = idx >> 5, col = (idx & 31) << 3;
            *(uint4*)(dsts[mtx] + r * LDQ + col) = *(const uint4*)(srcs[mtx] + (size_t)r * N_ + col);
        }
#pragma unroll
        for (int u = 0; u < 2; u++) {
            int idx = tid + u * 256;
            int r = 48 + (idx >> 5), col = (idx & 31) << 3;
            *(uint4*)(dsts[mtx] + r * LDQ + col) = make_uint4(0, 0, 0, 0);
        }
    }
    __syncthreads();

    int wr = wid & 1;
    int wc = wid >> 1;

#pragma unroll 1
    for (int nt = 0; nt < 4; nt++) {
        int n0 = nt * 64;

        wmma::fragment<wmma::accumulator, 16, 16, 16, float> sacc[2][4];
#pragma unroll
        for (int i = 0; i < 2; i++)
#pragma unroll
            for (int j = 0; j < 4; j++) wmma::fill_fragment(sacc[i][j], 0.f);
#pragma unroll
        for (int dk = 0; dk < 64; dk += 16) {
            wmma::fragment<wmma::matrix_a, 16, 16, 16, __nv_bfloat16, wmma::col_major> af[2];
            wmma::fragment<wmma::matrix_b, 16, 16, 16, __nv_bfloat16, wmma::row_major> bfr[4];
#pragma unroll
            for (int i = 0; i < 2; i++)
                wmma::load_matrix_sync(af[i], Qs + dk * LDQ + n0 + wr * 32 + i * 16, LDQ);
#pragma unroll
            for (int j = 0; j < 4; j++)
                wmma::load_matrix_sync(bfr[j], Ks + dk * LDQ + wc * 64 + j * 16, LDQ);
#pragma unroll
            for (int i = 0; i < 2; i++)
#pragma unroll
                for (int j = 0; j < 4; j++)
                    wmma::mma_sync(sacc[i][j], af[i], bfr[j], sacc[i][j]);
        }
        float* scr = scratch + wid * 256;
#pragma unroll
        for (int i = 0; i < 2; i++)
#pragma unroll
            for (int j = 0; j < 4; j++) {
                wmma::store_matrix_sync(scr, sacc[i][j], 16, wmma::mem_col_major);
                __syncwarp();
#pragma unroll
                for (int e = 0; e < 8; e++) {
                    int idx = lane + e * 32;
                    int ni = idx & 15, mj = idx >> 4;
                    STb[(wc * 64 + j * 16 + mj) * LDS + wr * 32 + i * 16 + ni] =
                        __float2bfloat16(scr[idx]);
                }
                __syncwarp();
            }
        __syncthreads();

        int dr = wid & 1;
        int nc = wid >> 1;
        wmma::fragment<wmma::accumulator, 16, 16, 16, float> oacc[2];
#pragma unroll
        for (int i = 0; i < 2; i++) wmma::fill_fragment(oacc[i], 0.f);
#pragma unroll
        for (int m = 0; m < 256; m += 16) {
            wmma::fragment<wmma::matrix_a, 16, 16, 16, __nv_bfloat16, wmma::row_major> av[2];
            wmma::fragment<wmma::matrix_b, 16, 16, 16, __nv_bfloat16, wmma::row_major> bs;
#pragma unroll
            for (int i = 0; i < 2; i++)
                wmma::load_matrix_sync(av[i], Vs + (dr * 32 + i * 16) * LDQ + m, LDQ);
            wmma::load_matrix_sync(bs, STb + m * LDS + nc * 16, LDS);
#pragma unroll
            for (int i = 0; i < 2; i++)
                wmma::mma_sync(oacc[i], av[i], bs, oacc[i]);
        }
#pragma unroll
        for (int i = 0; i < 2; i++) {
#pragma unroll
            for (int e = 0; e < oacc[i].num_elements; e++) oacc[i].x[e] *= 0.125f;
            wmma::store_matrix_sync(Osm + (dr * 32 + i * 16) * LDS + nc * 16,
                                    oacc[i], LDS, wmma::mem_row_major);
        }
        __syncthreads();

#pragma unroll
        for (int u = 0; u < 3; u++) {
            int e = tid + u * 256;
            int d = e >> 4, c4 = (e & 15) << 2;
            float4 val = *(float4*)(Osm + d * LDS + c4);
            *(float4*)(out + base + (size_t)d * N_ + n0 + c4) = val;
        }
        __syncthreads();
    }
}

// ---------------- launch ----------------------------------------------------------
extern "C" void kernel_launch(void* const* d_in, const int* in_sizes, int n_in,
                              void* d_out, int out_size)
{
    const float* x   = (const float*)d_in[0];
    const float* qw  = (const float*)d_in[2];
    const float* qg  = (const float*)d_in[3];
    const float* qb  = (const float*)d_in[4];
    const float* qm  = (const float*)d_in[5];
    const float* qv  = (const float*)d_in[6];
    const float* kw  = (const float*)d_in[7];
    const float* kg  = (const float*)d_in[8];
    const float* kb  = (const float*)d_in[9];
    const float* km  = (const float*)d_in[10];
    const float* kv  = (const float*)d_in[11];
    const float* vw  = (const float*)d_in[12];
    const float* vg  = (const float*)d_in[13];
    const float* vb  = (const float*)d_in[14];
    const float* vm  = (const float*)d_in[15];
    const float* vv  = (const float*)d_in[16];
    const float* pw  = (const float*)d_in[17];
    const float* pbias = (const float*)d_in[18];
    const float* pg  = (const float*)d_in[19];
    const float* pb  = (const float*)d_in[20];
    const float* pm  = (const float*)d_in[21];
    const float* pv  = (const float*)d_in[22];

    void *ps1, *psq, *psk, *psv, *ps2, *py3, *pya, *phi, *plo;
    cudaGetSymbolAddress(&ps1, g_s1);
    cudaGetSymbolAddress(&psq, g_sq);
    cudaGetSymbolAddress(&psk, g_sk);
    cudaGetSymbolAddress(&psv, g_sv);
    cudaGetSymbolAddress(&ps2, g_s2);
    cudaGetSymbolAddress(&py3, g_y3);
    cudaGetSymbolAddress(&pya, g_ya);
    cudaGetSymbolAddress(&phi, g_whi);
    cudaGetSymbolAddress(&plo, g_wlo);
    __nv_bfloat16* s1  = (__nv_bfloat16*)ps1;
    __nv_bfloat16* sq  = (__nv_bfloat16*)psq;
    __nv_bfloat16* sk  = (__nv_bfloat16*)psk;
    __nv_bfloat16* sv  = (__nv_bfloat16*)psv;
    __nv_bfloat16* s2  = (__nv_bfloat16*)ps2;
    float*         y3  = (float*)py3;
    float*         ya  = (float*)pya;
    __nv_bfloat16* whi = (__nv_bfloat16*)phi;
    __nv_bfloat16* wlo = (__nv_bfloat16*)plo;

    cudaFuncSetAttribute(gemm_bn_kernel, cudaFuncAttributeMaxDynamicSharedMemorySize, GSM);
    cudaFuncSetAttribute(attn_kernel, cudaFuncAttributeMaxDynamicSharedMemorySize, ASM_);

    wconv_kernel<<<(4 * C_ * C_ + 255) / 256, 256>>>(qw, kw, vw, pw);
    bnfold_kernel<<<6, 256>>>(qg, qb, qm, qv, kg, kb, km, kv,
                              vg, vb, vm, vv, pg, pb, pm, pv, pbias);
    lif_kernel<<<BCN_ / 256, 256>>>(x, s1);
    gemm_bn_kernel<<<dim3(M3_ / GBM, N_ / GBN, TB_), 256, GSM>>>(
        whi, wlo, s1, M3_, 0, y3);
    lif3_kernel<<<BON_ / 256, 256>>>(y3, sq, sk, sv);
    attn_kernel<<<TBH_, 256, ASM_>>>(sq, sk, sv, ya);
    lif_kernel<<<BCN_ / 256, 256>>>(ya, s2);
    gemm_bn_kernel<<<dim3(C_ / GBM, N_ / GBN, TB_), 256, GSM>>>(
        whi + 3 * C_ * C_, wlo + 3 * C_ * C_, s2, C_, 3 * C_, (float*)d_out);
}